// round 2
// baseline (speedup 1.0000x reference)
#include <cuda_runtime.h>
#include <cstdint>

typedef unsigned long long ull;

__device__ __forceinline__ ull fma2(ull a, ull b, ull c) {
    ull d;
    asm("fma.rn.f32x2 %0, %1, %2, %3;" : "=l"(d) : "l"(a), "l"(b), "l"(c));
    return d;
}
__device__ __forceinline__ float red2(ull v) {
    float lo = __uint_as_float((unsigned)(v & 0xffffffffu));
    float hi = __uint_as_float((unsigned)(v >> 32));
    return lo + hi;
}

// ---- smem layout (float offsets) ----
#define XS   68
#define WS1  68
#define YS1  98
#define YS2  50
#define YS3  26
#define YS4  14

#define OFF_XS   0
#define OFF_WS   (128 * XS)                 // 8704
#define OFF_Y1   0                          // 128*98 = 12544
#define OFF_W2E  12544
#define OFF_W2S  (OFF_W2E + 48 * YS1)       // 17248
#define OFF_W3E  (OFF_W2S + 48 * YS1)       // 21952
#define OFF_W3S  (OFF_W3E + 24 * YS2)       // 23152
#define OFF_W4E  (OFF_W3S + 24 * YS2)       // 24352
#define OFF_W4S  (OFF_W4E + 12 * YS3)       // 24664
#define OFF_W5S  (OFF_W4S + 12 * YS3)       // 24976
#define OFF_E5   (OFF_W5S + 24)             // 25000
#define OFF_Y2   25024                      // 128*50 = 6400 -> 31424
#define OFF_Y3   0                          // 128*26 = 3328
#define OFF_Y4   3328                       // 128*14 = 1792
#define SMEM_FLOATS 31424
#define SMEM_BYTES  (SMEM_FLOATS * 4)

// vec index: m = f(r,v); branch(e) iff (m&15)<8  (v<2 => e)
__device__ __forceinline__ int vmap(int r, int v) {
    return ((r & 3) << 1) | (v & 1) | ((v >> 1) << 3) | ((r >> 2) << 4);
}

// generic small GEMM on shared, f32x2 k-packed, relu epilogue
template<int MI, int NJ, int KP>
__device__ __forceinline__ void tail_gemm(float* sm, int abase, int aIstep,
                                          int bbase, int bJstep,
                                          int obase, int oIstep, int oJstep)
{
    ull acc[MI][NJ];
#pragma unroll
    for (int i = 0; i < MI; i++)
#pragma unroll
        for (int j = 0; j < NJ; j++) acc[i][j] = 0ull;

#pragma unroll 4
    for (int kp = 0; kp < KP; kp++) {
        int kk = kp * 2;
        ull b[NJ];
#pragma unroll
        for (int j = 0; j < NJ; j++)
            b[j] = *reinterpret_cast<const ull*>(&sm[bbase + j * bJstep + kk]);
#pragma unroll
        for (int i = 0; i < MI; i++) {
            ull a = *reinterpret_cast<const ull*>(&sm[abase + i * aIstep + kk]);
#pragma unroll
            for (int j = 0; j < NJ; j++) acc[i][j] = fma2(a, b[j], acc[i][j]);
        }
    }
#pragma unroll
    for (int i = 0; i < MI; i++)
#pragma unroll
        for (int j = 0; j < NJ; j++)
            sm[obase + i * oIstep + j * oJstep] = fmaxf(red2(acc[i][j]), 0.f);
}

__global__ __launch_bounds__(256, 1) void fused_net(
    const float* __restrict__ in,
    const float* __restrict__ sW1, const float* __restrict__ sW2,
    const float* __restrict__ sW3, const float* __restrict__ sW4,
    const float* __restrict__ sW5,
    const float* __restrict__ eW1, const float* __restrict__ eW2,
    const float* __restrict__ eW3, const float* __restrict__ eW4,
    const float* __restrict__ eW5,
    const float* __restrict__ s_seq, const float* __restrict__ s_pair,
    const float* __restrict__ e_seq, const float* __restrict__ e_pair,
    const float* __restrict__ cross_w,
    float* __restrict__ out)
{
    extern __shared__ float sm[];
    const int tid = threadIdx.x;
    const int r0  = blockIdx.x * 32;

    // pooling coefficients
    const float ep0 = e_pair[0], ep1 = e_pair[1];
    const float sp0 = s_pair[0], sp1 = s_pair[1];
    const float es0 = e_seq[0], es1 = e_seq[1], es2 = e_seq[2], es3 = e_seq[3];
    const float ss0 = s_seq[0], ss1 = s_seq[1], ss2 = s_seq[2], ss3 = s_seq[3];

    // ===================== Phase 1: pool+relu, layer1 GEMM (768->96 e&s) ====
    const int tm = tid >> 4;          // 0..15, m = tm + 16i (i 0..7)
    const int tn = tid & 15;          // 0..15, n = tn + 16j (j 0..5)
    const int wbase = (tm < 8) ? 0 : 96;
    const int wshift = ((tn >> 3) & 1) * 2;

    int aoff[8], boff[6];
#pragma unroll
    for (int i = 0; i < 8; i++) aoff[i] = OFF_XS + (tm + 16 * i) * XS;
#pragma unroll
    for (int j = 0; j < 6; j++) boff[j] = OFF_WS + (wbase + tn + 16 * j) * WS1 + wshift;

    ull acc[8][6];
#pragma unroll
    for (int i = 0; i < 8; i++)
#pragma unroll
        for (int j = 0; j < 6; j++) acc[i][j] = 0ull;

    for (int kc = 0; kc < 768; kc += 64) {
        __syncthreads();
        // weights: 192 rows x 32 float2 (row shifted by bit3 to kill conflicts)
#pragma unroll
        for (int it = 0; it < 24; it++) {
            int idx = tid + it * 256;
            int row = idx >> 5, k2 = idx & 31;
            const float* src = (row < 96) ? (eW1 + (size_t)row * 768)
                                          : (sW1 + (size_t)(row - 96) * 768);
            float2 v = *reinterpret_cast<const float2*>(src + kc + k2 * 2);
            *reinterpret_cast<float2*>(&sm[OFF_WS + row * WS1 + ((row >> 3) & 1) * 2 + k2 * 2]) = v;
        }
        // pooled X: 32 rows x 16 float4, 4 vecs each
#pragma unroll
        for (int it = 0; it < 2; it++) {
            int idx = tid + it * 256;
            int r = idx >> 4, k4 = idx & 15;
            const float4* p = reinterpret_cast<const float4*>(in + (size_t)(r0 + r) * 3072 + kc) + k4;
            float4 t0 = p[0], t1 = p[192], t2 = p[384], t3 = p[576];
            float4 q;
            q.x = fmaxf(ep0 * t0.x + ep1 * t2.x, 0.f);
            q.y = fmaxf(ep0 * t0.y + ep1 * t2.y, 0.f);
            q.z = fmaxf(ep0 * t0.z + ep1 * t2.z, 0.f);
            q.w = fmaxf(ep0 * t0.w + ep1 * t2.w, 0.f);
            *reinterpret_cast<float4*>(&sm[OFF_XS + vmap(r, 0) * XS + k4 * 4]) = q;
            q.x = fmaxf(es0 * t0.x + es1 * t1.x + es2 * t2.x + es3 * t3.x, 0.f);
            q.y = fmaxf(es0 * t0.y + es1 * t1.y + es2 * t2.y + es3 * t3.y, 0.f);
            q.z = fmaxf(es0 * t0.z + es1 * t1.z + es2 * t2.z + es3 * t3.z, 0.f);
            q.w = fmaxf(es0 * t0.w + es1 * t1.w + es2 * t2.w + es3 * t3.w, 0.f);
            *reinterpret_cast<float4*>(&sm[OFF_XS + vmap(r, 1) * XS + k4 * 4]) = q;
            q.x = fmaxf(sp0 * t0.x + sp1 * t2.x, 0.f);
            q.y = fmaxf(sp0 * t0.y + sp1 * t2.y, 0.f);
            q.z = fmaxf(sp0 * t0.z + sp1 * t2.z, 0.f);
            q.w = fmaxf(sp0 * t0.w + sp1 * t2.w, 0.f);
            *reinterpret_cast<float4*>(&sm[OFF_XS + vmap(r, 2) * XS + k4 * 4]) = q;
            q.x = fmaxf(ss0 * t0.x + ss1 * t1.x + ss2 * t2.x + ss3 * t3.x, 0.f);
            q.y = fmaxf(ss0 * t0.y + ss1 * t1.y + ss2 * t2.y + ss3 * t3.y, 0.f);
            q.z = fmaxf(ss0 * t0.z + ss1 * t1.z + ss2 * t2.z + ss3 * t3.z, 0.f);
            q.w = fmaxf(ss0 * t0.w + ss1 * t1.w + ss2 * t2.w + ss3 * t3.w, 0.f);
            *reinterpret_cast<float4*>(&sm[OFF_XS + vmap(r, 3) * XS + k4 * 4]) = q;
        }
        __syncthreads();
#pragma unroll 8
        for (int kk = 0; kk < 64; kk += 2) {
            ull b[6];
#pragma unroll
            for (int j = 0; j < 6; j++)
                b[j] = *reinterpret_cast<const ull*>(&sm[boff[j] + kk]);
#pragma unroll
            for (int i = 0; i < 8; i++) {
                ull a = *reinterpret_cast<const ull*>(&sm[aoff[i] + kk]);
#pragma unroll
                for (int j = 0; j < 6; j++) acc[i][j] = fma2(a, b[j], acc[i][j]);
            }
        }
    }
    __syncthreads();   // phase-1 smem now dead everywhere

    // write relu(y1) -> Ys1[m][n]
#pragma unroll
    for (int i = 0; i < 8; i++)
#pragma unroll
        for (int j = 0; j < 6; j++)
            sm[OFF_Y1 + (tm + 16 * i) * YS1 + (tn + 16 * j)] = fmaxf(red2(acc[i][j]), 0.f);

    // load tail weights into shared
    for (int idx = tid; idx < 2304; idx += 256) {       // W2: 48 rows x 48 float2
        int n = idx / 48, k2 = idx % 48;
        *reinterpret_cast<float2*>(&sm[OFF_W2E + n * YS1 + 2 * k2]) =
            *reinterpret_cast<const float2*>(eW2 + n * 96 + 2 * k2);
        *reinterpret_cast<float2*>(&sm[OFF_W2S + n * YS1 + 2 * k2]) =
            *reinterpret_cast<const float2*>(sW2 + n * 96 + 2 * k2);
    }
    for (int idx = tid; idx < 576; idx += 256) {        // W3: 24 rows x 24 float2
        int n = idx / 24, k2 = idx % 24;
        *reinterpret_cast<float2*>(&sm[OFF_W3E + n * YS2 + 2 * k2]) =
            *reinterpret_cast<const float2*>(eW3 + n * 48 + 2 * k2);
        *reinterpret_cast<float2*>(&sm[OFF_W3S + n * YS2 + 2 * k2]) =
            *reinterpret_cast<const float2*>(sW3 + n * 48 + 2 * k2);
    }
    if (tid < 144) {                                    // W4: 12 rows x 12 float2
        int n = tid / 12, k2 = tid % 12;
        *reinterpret_cast<float2*>(&sm[OFF_W4E + n * YS3 + 2 * k2]) =
            *reinterpret_cast<const float2*>(eW4 + n * 24 + 2 * k2);
        *reinterpret_cast<float2*>(&sm[OFF_W4S + n * YS3 + 2 * k2]) =
            *reinterpret_cast<const float2*>(sW4 + n * 24 + 2 * k2);
    }
    if (tid >= 160 && tid < 184) sm[OFF_W5S + tid - 160] = sW5[tid - 160];
    if (tid >= 192 && tid < 204) {
        int k = tid - 192;
        float s = 0.f;
#pragma unroll
        for (int h = 0; h < 8; h++) s += eW5[h * 12 + k];
        sm[OFF_E5 + k] = s;
    }
    __syncthreads();

    // ===================== Phase 2: layers 2..4 ============================
    {
        const int tm2 = tid >> 3;     // 0..31, m = tm2 + 32i
        const int tn2 = tid & 7;
        const bool is_e = (tm2 & 15) < 8;
        // layer 2: 96 -> 48
        tail_gemm<4, 6, 48>(sm,
            OFF_Y1 + tm2 * YS1, 32 * YS1,
            (is_e ? OFF_W2E : OFF_W2S) + tn2 * YS1, 8 * YS1,
            OFF_Y2 + tm2 * YS2 + tn2, 32 * YS2, 8);
        __syncthreads();
        // layer 3: 48 -> 24
        tail_gemm<4, 3, 24>(sm,
            OFF_Y2 + tm2 * YS2, 32 * YS2,
            (is_e ? OFF_W3E : OFF_W3S) + tn2 * YS2, 8 * YS2,
            OFF_Y3 + tm2 * YS3 + tn2, 32 * YS3, 8);
        __syncthreads();
    }
    {
        const int tm3 = tid >> 2;     // 0..63, m = tm3 + 64i
        const int tn3 = tid & 3;
        const bool is_e = (tm3 & 15) < 8;
        // layer 4: 24 -> 12
        tail_gemm<2, 3, 12>(sm,
            OFF_Y3 + tm3 * YS3, 64 * YS3,
            (is_e ? OFF_W4E : OFF_W4S) + tn3 * YS3, 4 * YS3,
            OFF_Y4 + tm3 * YS4 + tn3, 64 * YS4, 4);
        __syncthreads();
    }

    // ===================== Final: W5 dots + cross combine ==================
    if (tid < 32) {
        const int r = tid;
        const float cw0 = cross_w[0], cw1 = cross_w[1];
        const float* cpe = &sm[OFF_Y4 + vmap(r, 0) * YS4];
        const float* cse = &sm[OFF_Y4 + vmap(r, 1) * YS4];
        const float* cps = &sm[OFF_Y4 + vmap(r, 2) * YS4];
        const float* css = &sm[OFF_Y4 + vmap(r, 3) * YS4];
        float SeP = 0.f, SeS = 0.f;
        float t0p = 0.f, t1p = 0.f, t0s = 0.f, t1s = 0.f;
#pragma unroll
        for (int k = 0; k < 12; k++) {
            float e5 = sm[OFF_E5 + k];
            float w0 = sm[OFF_W5S + k];
            float w1 = sm[OFF_W5S + 12 + k];
            SeP = fmaf(cpe[k], e5, SeP);
            SeS = fmaf(cse[k], e5, SeS);
            t0p = fmaf(cps[k], w0, t0p);
            t1p = fmaf(cps[k], w1, t1p);
            t0s = fmaf(css[k], w0, t0s);
            t1s = fmaf(css[k], w1, t1s);
        }
        float o0 = cw0 * SeP * t0p + cw1 * SeS * t0s;
        float o1 = cw0 * SeP * t1p + cw1 * SeS * t1s;
        out[(size_t)(r0 + r) * 2 + 0] = o0;
        out[(size_t)(r0 + r) * 2 + 1] = o1;
    }
}

extern "C" void kernel_launch(void* const* d_in, const int* in_sizes, int n_in,
                              void* d_out, int out_size)
{
    const float* in      = (const float*)d_in[0];
    const float* sW1     = (const float*)d_in[1];
    const float* sW2     = (const float*)d_in[2];
    const float* sW3     = (const float*)d_in[3];
    const float* sW4     = (const float*)d_in[4];
    const float* sW5     = (const float*)d_in[5];
    const float* eW1     = (const float*)d_in[6];
    const float* eW2     = (const float*)d_in[7];
    const float* eW3     = (const float*)d_in[8];
    const float* eW4     = (const float*)d_in[9];
    const float* eW5     = (const float*)d_in[10];
    const float* s_seq   = (const float*)d_in[11];
    const float* s_pair  = (const float*)d_in[12];
    const float* e_seq   = (const float*)d_in[13];
    const float* e_pair  = (const float*)d_in[14];
    const float* cross_w = (const float*)d_in[15];
    float* out = (float*)d_out;

    const int B = in_sizes[0] / 3072;   // 65536

    static int smem_set = 0;
    if (!smem_set) {
        cudaFuncSetAttribute(fused_net, cudaFuncAttributeMaxDynamicSharedMemorySize, SMEM_BYTES);
        smem_set = 1;
    }
    fused_net<<<B / 32, 256, SMEM_BYTES>>>(
        in, sW1, sW2, sW3, sW4, sW5, eW1, eW2, eW3, eW4, eW5,
        s_seq, s_pair, e_seq, e_pair, cross_w, out);
}